// round 1
// baseline (speedup 1.0000x reference)
#include <cuda_runtime.h>
#include <cuda_bf16.h>
#include <mma.h>

using namespace nvcuda;

// Problem constants (fixed by setup_inputs)
#define N_ROWS 8192
#define D_DIM  512
static constexpr float INV_T = 14.285714285714286f;  // 1/0.07

// Scratch (no cudaMalloc allowed): normalized features (bf16), per-row stats
static __device__ __nv_bfloat16 g_fnb[N_ROWS * D_DIM];   // 8 MB
static __device__ float g_m[N_ROWS];
static __device__ float g_P[N_ROWS];
static __device__ float g_S[N_ROWS];
static __device__ float g_C[N_ROWS];

// ---------------------------------------------------------------------------
// Kernel 1: row L2-normalize (fp32), emit bf16 fn, per-row m_i = ||fn||^2 / T,
// and zero the accumulators (graph replays must be self-resetting).
// 8192 blocks x 128 threads; each thread owns one float4 of the row.
// ---------------------------------------------------------------------------
__global__ void normalize_kernel(const float* __restrict__ feat) {
    const int r   = blockIdx.x;
    const int tid = threadIdx.x;
    __shared__ float sbuf[4];

    const float4 f4 = reinterpret_cast<const float4*>(feat + (size_t)r * D_DIM)[tid];
    float ss = f4.x * f4.x + f4.y * f4.y + f4.z * f4.z + f4.w * f4.w;
    #pragma unroll
    for (int o = 16; o; o >>= 1) ss += __shfl_xor_sync(0xffffffffu, ss, o);
    if ((tid & 31) == 0) sbuf[tid >> 5] = ss;
    __syncthreads();
    const float tot  = sbuf[0] + sbuf[1] + sbuf[2] + sbuf[3];
    const float norm = fmaxf(sqrtf(tot), 1e-8f);

    float4 fn;
    fn.x = f4.x / norm;
    fn.y = f4.y / norm;
    fn.z = f4.z / norm;
    fn.w = f4.w / norm;

    float ss2 = fn.x * fn.x + fn.y * fn.y + fn.z * fn.z + fn.w * fn.w;
    #pragma unroll
    for (int o = 16; o; o >>= 1) ss2 += __shfl_xor_sync(0xffffffffu, ss2, o);
    __syncthreads();   // everyone done reading sbuf
    if ((tid & 31) == 0) sbuf[tid >> 5] = ss2;
    __syncthreads();
    const float m = (sbuf[0] + sbuf[1] + sbuf[2] + sbuf[3]) * INV_T;

    __nv_bfloat162* dst =
        reinterpret_cast<__nv_bfloat162*>(g_fnb + (size_t)r * D_DIM) + tid * 2;
    dst[0] = __floats2bfloat162_rn(fn.x, fn.y);
    dst[1] = __floats2bfloat162_rn(fn.z, fn.w);

    if (tid == 0) {
        g_m[r] = m;
        g_P[r] = 0.f;
        g_S[r] = 0.f;
        g_C[r] = 0.f;
    }
}

// ---------------------------------------------------------------------------
// Kernel 2: fused sim-GEMM (bf16 HMMA, fp32 accum) + exp/masked-sum epilogue.
// Grid 64x64 tiles of 128x128. 256 threads = 8 warps, warp grid 4(M) x 2(N),
// each warp computes a 32x64 sub-tile as 2x4 wmma 16x16x16 fragments.
//
// Shared memory layout (dynamic, union across phases):
//   GEMM phase:     sA[128][72] bf16 (18432 B) | sB[128][72] bf16 (18432 B)
//   Epilogue phase: cbuf: 8 warps x 32x68 fp32  (69632 B)
//                   pk:   packed masks 128 x 132 bytes (16896 B) @ 69632
//   Total = 86528 B.
// ---------------------------------------------------------------------------
#define SMEM_BYTES 86528

__global__ __launch_bounds__(256)
void simloss_kernel(const int* __restrict__ pos, const int* __restrict__ neg) {
    extern __shared__ char smem[];
    const int tid    = threadIdx.x;
    const int wid    = tid >> 5;
    const int lane   = tid & 31;
    const int warp_m = wid >> 1;   // 0..3
    const int warp_n = wid & 1;    // 0..1
    const int i0 = blockIdx.y * 128;
    const int j0 = blockIdx.x * 128;

    wmma::fragment<wmma::accumulator, 16, 16, 16, float> acc[2][4];
    #pragma unroll
    for (int m = 0; m < 2; m++)
        #pragma unroll
        for (int n = 0; n < 4; n++) wmma::fill_fragment(acc[m][n], 0.0f);

    __nv_bfloat16* sA = reinterpret_cast<__nv_bfloat16*>(smem);
    __nv_bfloat16* sB = reinterpret_cast<__nv_bfloat16*>(smem + 18432);

    for (int kc = 0; kc < D_DIM; kc += 64) {
        const __nv_bfloat16* gA = g_fnb + (size_t)i0 * D_DIM + kc;
        const __nv_bfloat16* gB = g_fnb + (size_t)j0 * D_DIM + kc;
        // 128 rows x 64 cols bf16 per tile = 1024 uint4; 4 per thread.
        #pragma unroll
        for (int it = 0; it < 4; ++it) {
            const int t = tid + it * 256;
            const int r = t >> 3, c = t & 7;
            *reinterpret_cast<uint4*>(sA + r * 72 + c * 8) =
                *reinterpret_cast<const uint4*>(gA + (size_t)r * D_DIM + c * 8);
            *reinterpret_cast<uint4*>(sB + r * 72 + c * 8) =
                *reinterpret_cast<const uint4*>(gB + (size_t)r * D_DIM + c * 8);
        }
        __syncthreads();

        #pragma unroll
        for (int kk = 0; kk < 64; kk += 16) {
            wmma::fragment<wmma::matrix_a, 16, 16, 16, __nv_bfloat16, wmma::row_major> a[2];
            wmma::load_matrix_sync(a[0], sA + (warp_m * 32)      * 72 + kk, 72);
            wmma::load_matrix_sync(a[1], sA + (warp_m * 32 + 16) * 72 + kk, 72);
            #pragma unroll
            for (int n = 0; n < 4; n++) {
                wmma::fragment<wmma::matrix_b, 16, 16, 16, __nv_bfloat16, wmma::col_major> b;
                wmma::load_matrix_sync(b, sB + (warp_n * 64 + n * 16) * 72 + kk, 72);
                wmma::mma_sync(acc[0][n], a[0], b, acc[0][n]);
                wmma::mma_sync(acc[1][n], a[1], b, acc[1][n]);
            }
        }
        __syncthreads();
    }

    // ---- Epilogue ----
    // Stage this warp's 32x64 fp32 result (stride 68 -> 4-way conflict max).
    float* cbuf = reinterpret_cast<float*>(smem) + wid * (32 * 68);
    #pragma unroll
    for (int m = 0; m < 2; m++)
        #pragma unroll
        for (int n = 0; n < 4; n++)
            wmma::store_matrix_sync(cbuf + m * 16 * 68 + n * 16, acc[m][n], 68,
                                    wmma::mem_row_major);

    // Build packed mask tile (coalesced int4 global reads, diag zeroed).
    unsigned char* pk = reinterpret_cast<unsigned char*>(smem) + 69632;
    #pragma unroll
    for (int it = 0; it < 16; ++it) {
        const int t = tid + it * 256;          // 128 rows x 32 int4-groups
        const int r = t >> 5, g = t & 31;
        const int gi = i0 + r;
        const int gj = j0 + g * 4;
        const size_t base = (size_t)gi * N_ROWS + gj;
        const int4 p = *reinterpret_cast<const int4*>(pos + base);
        const int4 q = *reinterpret_cast<const int4*>(neg + base);
        uchar4 o;
        o.x = (gi != gj    ) ? (unsigned char)(((p.x != 0) ? 1 : 0) | ((q.x != 0) ? 2 : 0)) : 0;
        o.y = (gi != gj + 1) ? (unsigned char)(((p.y != 0) ? 1 : 0) | ((q.y != 0) ? 2 : 0)) : 0;
        o.z = (gi != gj + 2) ? (unsigned char)(((p.z != 0) ? 1 : 0) | ((q.z != 0) ? 2 : 0)) : 0;
        o.w = (gi != gj + 3) ? (unsigned char)(((p.w != 0) ? 1 : 0) | ((q.w != 0) ? 2 : 0)) : 0;
        *reinterpret_cast<uchar4*>(pk + r * 132 + g * 4) = o;
    }
    __syncthreads();

    // Lane-per-row exp + masked sums over this warp's 64 columns.
    const int   li  = warp_m * 32 + lane;   // local row 0..127
    const int   gi2 = i0 + li;
    const float mi  = g_m[gi2];
    const float* crow = cbuf + lane * 68;
    const unsigned char* prow = pk + (size_t)li * 132 + warp_n * 64;

    float P = 0.f, S = 0.f, C = 0.f;
    #pragma unroll 8
    for (int c = 0; c < 64; c++) {
        const float e = __expf(fmaf(crow[c], INV_T, -mi));
        const unsigned char b = prow[c];
        if (b & 1) { P += e; C += 1.f; }
        if (b & 2) { S += e; }
    }
    atomicAdd(&g_P[gi2], P);
    atomicAdd(&g_S[gi2], S);
    atomicAdd(&g_C[gi2], C);
}

// ---------------------------------------------------------------------------
// Kernel 3: per-row loss + mean. Single block.
// loss_i = -(P_i - C_i * log(S_i)) / max(C_i, 1)
// ---------------------------------------------------------------------------
__global__ void finalize_kernel(float* __restrict__ out) {
    __shared__ float sbuf[32];
    const int tid = threadIdx.x;
    float local = 0.f;
    for (int i = tid; i < N_ROWS; i += 1024) {
        const float C = g_C[i];
        const float P = g_P[i];
        const float S = g_S[i];
        const float L = logf(S);
        const float card = (C == 0.f) ? 1.f : C;
        local += -(P - C * L) / card;
    }
    #pragma unroll
    for (int o = 16; o; o >>= 1) local += __shfl_xor_sync(0xffffffffu, local, o);
    if ((tid & 31) == 0) sbuf[tid >> 5] = local;
    __syncthreads();
    if (tid < 32) {
        float v = sbuf[tid];
        #pragma unroll
        for (int o = 16; o; o >>= 1) v += __shfl_xor_sync(0xffffffffu, v, o);
        if (tid == 0) out[0] = v * (1.0f / (float)N_ROWS);
    }
}

// ---------------------------------------------------------------------------
extern "C" void kernel_launch(void* const* d_in, const int* in_sizes, int n_in,
                              void* d_out, int out_size) {
    const float* feat = (const float*)d_in[0];
    const int*   pos  = (const int*)d_in[1];
    const int*   neg  = (const int*)d_in[2];
    float*       out  = (float*)d_out;

    cudaFuncSetAttribute(simloss_kernel,
                         cudaFuncAttributeMaxDynamicSharedMemorySize, SMEM_BYTES);

    normalize_kernel<<<N_ROWS, 128>>>(feat);

    dim3 grid(N_ROWS / 128, N_ROWS / 128);
    simloss_kernel<<<grid, 256, SMEM_BYTES>>>(pos, neg);

    finalize_kernel<<<1, 1024>>>(out);
}

// round 3
// speedup vs baseline: 1.3659x; 1.3659x over previous
#include <cuda_runtime.h>
#include <cuda_bf16.h>
#include <cstdint>

// Problem constants (fixed by setup_inputs)
#define N_ROWS 8192
#define D_DIM  512
static constexpr float INV_T = 14.285714285714286f;  // 1/0.07

// Scratch (no cudaMalloc allowed)
static __device__ __nv_bfloat16 g_fnb[N_ROWS * D_DIM];   // 8 MB normalized bf16
static __device__ float g_m[N_ROWS];
static __device__ float g_P[N_ROWS];
static __device__ float g_S[N_ROWS];
static __device__ float g_C[N_ROWS];

// ---------------------------------------------------------------------------
// Helpers
// ---------------------------------------------------------------------------
__device__ __forceinline__ uint32_t smem_u32(const void* p) {
    uint32_t a;
    asm("{ .reg .u64 t; cvta.to.shared.u64 t, %1; cvt.u32.u64 %0, t; }" : "=r"(a) : "l"(p));
    return a;
}
// SW128 swizzle (Swizzle<3,4,3>) on byte offsets within a 128B-row tile
__device__ __forceinline__ uint32_t sw128(uint32_t off) { return off ^ ((off >> 3) & 0x70); }

__device__ __forceinline__ void ldsm_x4(uint32_t* r, uint32_t addr) {
    asm volatile("ldmatrix.sync.aligned.m8n8.x4.shared.b16 {%0,%1,%2,%3}, [%4];"
                 : "=r"(r[0]), "=r"(r[1]), "=r"(r[2]), "=r"(r[3]) : "r"(addr));
}
__device__ __forceinline__ void mma16816(float* c, const uint32_t* a, const uint32_t* b) {
    asm volatile(
        "mma.sync.aligned.m16n8k16.row.col.f32.bf16.bf16.f32 "
        "{%0,%1,%2,%3}, {%4,%5,%6,%7}, {%8,%9}, {%0,%1,%2,%3};"
        : "+f"(c[0]), "+f"(c[1]), "+f"(c[2]), "+f"(c[3])
        : "r"(a[0]), "r"(a[1]), "r"(a[2]), "r"(a[3]), "r"(b[0]), "r"(b[1]));
}
#define CP16(dst, src) \
    asm volatile("cp.async.cg.shared.global [%0], [%1], 16;" :: "r"(dst), "l"(src))
#define CP_COMMIT() asm volatile("cp.async.commit_group;")
#define CP_WAIT0()  asm volatile("cp.async.wait_group 0;")

// ---------------------------------------------------------------------------
// Kernel 1: row L2-normalize, bf16 emit, m_i = ||fn||^2/T, zero accumulators.
// ---------------------------------------------------------------------------
__global__ void normalize_kernel(const float* __restrict__ feat) {
    const int r   = blockIdx.x;
    const int tid = threadIdx.x;
    __shared__ float sbuf[4];

    const float4 f4 = reinterpret_cast<const float4*>(feat + (size_t)r * D_DIM)[tid];
    float ss = f4.x * f4.x + f4.y * f4.y + f4.z * f4.z + f4.w * f4.w;
    #pragma unroll
    for (int o = 16; o; o >>= 1) ss += __shfl_xor_sync(0xffffffffu, ss, o);
    if ((tid & 31) == 0) sbuf[tid >> 5] = ss;
    __syncthreads();
    const float tot  = sbuf[0] + sbuf[1] + sbuf[2] + sbuf[3];
    const float norm = fmaxf(sqrtf(tot), 1e-8f);

    float4 fn;
    fn.x = f4.x / norm; fn.y = f4.y / norm; fn.z = f4.z / norm; fn.w = f4.w / norm;

    float ss2 = fn.x * fn.x + fn.y * fn.y + fn.z * fn.z + fn.w * fn.w;
    #pragma unroll
    for (int o = 16; o; o >>= 1) ss2 += __shfl_xor_sync(0xffffffffu, ss2, o);
    __syncthreads();
    if ((tid & 31) == 0) sbuf[tid >> 5] = ss2;
    __syncthreads();
    const float m = (sbuf[0] + sbuf[1] + sbuf[2] + sbuf[3]) * INV_T;

    __nv_bfloat162* dst =
        reinterpret_cast<__nv_bfloat162*>(g_fnb + (size_t)r * D_DIM) + tid * 2;
    dst[0] = __floats2bfloat162_rn(fn.x, fn.y);
    dst[1] = __floats2bfloat162_rn(fn.z, fn.w);

    if (tid == 0) { g_m[r] = m; g_P[r] = 0.f; g_S[r] = 0.f; g_C[r] = 0.f; }
}

// ---------------------------------------------------------------------------
// Kernel 2: hand-rolled bf16 mma.sync GEMM + fused exp/masked-sum epilogue.
// CTA 128x128 tile, 8 warps (4m x 2n), warp tile 32x64 = 2x8 m16n8 frags.
// K chunks of 64, cp.async double-buffered; mask packing interleaved.
//
// SMEM: A bufs 2x16384 @0 | B bufs 2x16384 @32768 | pk 128x132 @65536
// ---------------------------------------------------------------------------
#define SM_A  0
#define SM_B  32768
#define SM_PK 65536
#define SMEM_BYTES (65536 + 16896)
#define K_CHUNK 64
#define N_CHUNKS (D_DIM / K_CHUNK)

__global__ __launch_bounds__(256, 2)
void simloss_mma_kernel(const int* __restrict__ pos, const int* __restrict__ neg) {
    extern __shared__ char smem[];
    const uint32_t sb  = smem_u32(smem);
    const int tid    = threadIdx.x;
    const int wid    = tid >> 5;
    const int lane   = tid & 31;
    const int warp_m = wid >> 1;   // 0..3
    const int warp_n = wid & 1;    // 0..1
    const int i0 = blockIdx.y * 128;
    const int j0 = blockIdx.x * 128;

    float acc[2][8][4];
    #pragma unroll
    for (int m = 0; m < 2; m++)
        #pragma unroll
        for (int n = 0; n < 8; n++)
            #pragma unroll
            for (int k = 0; k < 4; k++) acc[m][n][k] = 0.f;

    // cp.async staging of one K chunk (A+B, 8 x 16B per thread)
    const int st_r = tid >> 3;          // 0..31 (x4 iters -> rows)
    const int st_q = tid & 7;           // 16B col within 128B row
    auto stage = [&](int c) {
        const int b  = c & 1;
        const int kc = c * K_CHUNK;
        const __nv_bfloat16* gA = g_fnb + (size_t)i0 * D_DIM + kc;
        const __nv_bfloat16* gB = g_fnb + (size_t)j0 * D_DIM + kc;
        const uint32_t ab = sb + SM_A + b * 16384;
        const uint32_t bb = sb + SM_B + b * 16384;
        #pragma unroll
        for (int it = 0; it < 4; ++it) {
            const int r = st_r + it * 32;
            const uint32_t so = sw128(r * 128 + st_q * 16);
            CP16(ab + so, gA + (size_t)r * D_DIM + st_q * 8);
            CP16(bb + so, gB + (size_t)r * D_DIM + st_q * 8);
        }
        CP_COMMIT();
    };

    unsigned char* pk = reinterpret_cast<unsigned char*>(smem) + SM_PK;

    stage(0);

    // ldmatrix lane-address components (constant across kk)
    const int a_row8 = (lane & 7) + ((lane >> 3) & 1) * 8;  // row within m16
    const int a_kb16 = (lane >> 4) * 16;                    // k-half byte offset
    const int b_row8 = ((lane >> 4) & 1) * 8 + (lane & 7);  // n within n16
    const int b_kb16 = ((lane >> 3) & 1) * 16;

    for (int c = 0; c < N_CHUNKS; ++c) {
        CP_WAIT0();
        __syncthreads();
        if (c + 1 < N_CHUNKS) stage(c + 1);

        // --- mask pack: issue LDGs now, pack after the mma block ---
        int4 mp[2], mq[2];
        int mr[2], mg[2];
        #pragma unroll
        for (int u = 0; u < 2; ++u) {
            const int t = tid + (c * 2 + u) * 256;   // 128 rows x 32 int4-groups
            mr[u] = t >> 5;  mg[u] = t & 31;
            const size_t base = (size_t)(i0 + mr[u]) * N_ROWS + (j0 + mg[u] * 4);
            mp[u] = *reinterpret_cast<const int4*>(pos + base);
            mq[u] = *reinterpret_cast<const int4*>(neg + base);
        }

        // --- mma over this chunk ---
        const int b = c & 1;
        const uint32_t ab = sb + SM_A + b * 16384;
        const uint32_t bb = sb + SM_B + b * 16384;
        #pragma unroll
        for (int kk = 0; kk < K_CHUNK; kk += 16) {
            uint32_t afr[2][4];
            #pragma unroll
            for (int tm = 0; tm < 2; ++tm) {
                const int row = warp_m * 32 + tm * 16 + a_row8;
                ldsm_x4(afr[tm], ab + sw128(row * 128 + kk * 2 + a_kb16));
            }
            uint32_t bfr[4][4];
            #pragma unroll
            for (int tb = 0; tb < 4; ++tb) {
                const int nr = warp_n * 64 + tb * 16 + b_row8;
                ldsm_x4(bfr[tb], bb + sw128(nr * 128 + kk * 2 + b_kb16));
            }
            #pragma unroll
            for (int tm = 0; tm < 2; ++tm)
                #pragma unroll
                for (int tn = 0; tn < 8; ++tn)
                    mma16816(acc[tm][tn], afr[tm], &bfr[tn >> 1][(tn & 1) * 2]);
        }

        // --- pack masks to smem ---
        #pragma unroll
        for (int u = 0; u < 2; ++u) {
            const int gi = i0 + mr[u];
            const int gj = j0 + mg[u] * 4;
            uchar4 o;
            o.x = (gi != gj    ) ? (unsigned char)(((mp[u].x != 0) ? 1 : 0) | ((mq[u].x != 0) ? 2 : 0)) : 0;
            o.y = (gi != gj + 1) ? (unsigned char)(((mp[u].y != 0) ? 1 : 0) | ((mq[u].y != 0) ? 2 : 0)) : 0;
            o.z = (gi != gj + 2) ? (unsigned char)(((mp[u].z != 0) ? 1 : 0) | ((mq[u].z != 0) ? 2 : 0)) : 0;
            o.w = (gi != gj + 3) ? (unsigned char)(((mp[u].w != 0) ? 1 : 0) | ((mq[u].w != 0) ? 2 : 0)) : 0;
            *reinterpret_cast<uchar4*>(pk + mr[u] * 132 + mg[u] * 4) = o;
        }
    }
    __syncthreads();   // pk complete, all warps done

    // ---- Register-resident epilogue ----
    // Fragment map: tile (tm,tn): rows r0 = warp_m*32+tm*16+(lane>>2), r1 = r0+8;
    // cols cb = warp_n*64+tn*8+(lane&3)*2; acc[.][0..1] -> (r0,cb),(r0,cb+1);
    // acc[.][2..3] -> (r1,cb),(r1,cb+1).
    #pragma unroll
    for (int tm = 0; tm < 2; ++tm) {
        const int r0 = warp_m * 32 + tm * 16 + (lane >> 2);
        const int r1 = r0 + 8;
        const float m0 = g_m[i0 + r0];
        const float m1 = g_m[i0 + r1];
        float P0 = 0.f, S0 = 0.f, C0 = 0.f, P1 = 0.f, S1 = 0.f, C1 = 0.f;
        #pragma unroll
        for (int tn = 0; tn < 8; ++tn) {
            const int cb = warp_n * 64 + tn * 8 + (lane & 3) * 2;
            const unsigned char b00 = pk[r0 * 132 + cb];
            const unsigned char b01 = pk[r0 * 132 + cb + 1];
            const unsigned char b10 = pk[r1 * 132 + cb];
            const unsigned char b11 = pk[r1 * 132 + cb + 1];
            const float e00 = __expf(fmaf(acc[tm][tn][0], INV_T, -m0));
            const float e01 = __expf(fmaf(acc[tm][tn][1], INV_T, -m0));
            const float e10 = __expf(fmaf(acc[tm][tn][2], INV_T, -m1));
            const float e11 = __expf(fmaf(acc[tm][tn][3], INV_T, -m1));
            if (b00 & 1) { P0 += e00; C0 += 1.f; }
            if (b00 & 2) { S0 += e00; }
            if (b01 & 1) { P0 += e01; C0 += 1.f; }
            if (b01 & 2) { S0 += e01; }
            if (b10 & 1) { P1 += e10; C1 += 1.f; }
            if (b10 & 2) { S1 += e10; }
            if (b11 & 1) { P1 += e11; C1 += 1.f; }
            if (b11 & 2) { S1 += e11; }
        }
        // quad reduce (lanes sharing the same row)
        #pragma unroll
        for (int o = 1; o < 4; o <<= 1) {
            P0 += __shfl_xor_sync(0xffffffffu, P0, o);
            S0 += __shfl_xor_sync(0xffffffffu, S0, o);
            C0 += __shfl_xor_sync(0xffffffffu, C0, o);
            P1 += __shfl_xor_sync(0xffffffffu, P1, o);
            S1 += __shfl_xor_sync(0xffffffffu, S1, o);
            C1 += __shfl_xor_sync(0xffffffffu, C1, o);
        }
        if ((lane & 3) == 0) {
            atomicAdd(&g_P[i0 + r0], P0);
            atomicAdd(&g_S[i0 + r0], S0);
            atomicAdd(&g_C[i0 + r0], C0);
            atomicAdd(&g_P[i0 + r1], P1);
            atomicAdd(&g_S[i0 + r1], S1);
            atomicAdd(&g_C[i0 + r1], C1);
        }
    }
}

// ---------------------------------------------------------------------------
// Kernel 3: per-row loss + mean.
// ---------------------------------------------------------------------------
__global__ void finalize_kernel(float* __restrict__ out) {
    __shared__ float sbuf[32];
    const int tid = threadIdx.x;
    float local = 0.f;
    for (int i = tid; i < N_ROWS; i += 1024) {
        const float C = g_C[i];
        const float P = g_P[i];
        const float S = g_S[i];
        const float L = logf(S);
        const float card = (C == 0.f) ? 1.f : C;
        local += -(P - C * L) / card;
    }
    #pragma unroll
    for (int o = 16; o; o >>= 1) local += __shfl_xor_sync(0xffffffffu, local, o);
    if ((tid & 31) == 0) sbuf[tid >> 5] = local;
    __syncthreads();
    if (tid < 32) {
        float v = sbuf[tid];
        #pragma unroll
        for (int o = 16; o; o >>= 1) v += __shfl_xor_sync(0xffffffffu, v, o);
        if (tid == 0) out[0] = v * (1.0f / (float)N_ROWS);
    }
}

// ---------------------------------------------------------------------------
extern "C" void kernel_launch(void* const* d_in, const int* in_sizes, int n_in,
                              void* d_out, int out_size) {
    const float* feat = (const float*)d_in[0];
    const int*   pos  = (const int*)d_in[1];
    const int*   neg  = (const int*)d_in[2];
    float*       out  = (float*)d_out;

    cudaFuncSetAttribute(simloss_mma_kernel,
                         cudaFuncAttributeMaxDynamicSharedMemorySize, SMEM_BYTES);

    normalize_kernel<<<N_ROWS, 128>>>(feat);

    dim3 grid(N_ROWS / 128, N_ROWS / 128);
    simloss_mma_kernel<<<grid, 256, SMEM_BYTES>>>(pos, neg);

    finalize_kernel<<<1, 1024>>>(out);
}

// round 4
// speedup vs baseline: 1.4624x; 1.0706x over previous
#include <cuda_runtime.h>
#include <cuda_bf16.h>
#include <cstdint>

// Problem constants (fixed by setup_inputs)
#define N_ROWS 8192
#define D_DIM  512
static constexpr float INV_T = 14.285714285714286f;  // 1/0.07

// Scratch (no cudaMalloc allowed)
static __device__ __nv_bfloat16 g_fnb[N_ROWS * D_DIM];   // 8 MB normalized bf16
static __device__ float g_em[N_ROWS];                    // exp(-m_i)
static __device__ float g_P[N_ROWS];
static __device__ float g_S[N_ROWS];
static __device__ float g_C[N_ROWS];

// ---------------------------------------------------------------------------
// Helpers
// ---------------------------------------------------------------------------
__device__ __forceinline__ uint32_t smem_u32(const void* p) {
    uint32_t a;
    asm("{ .reg .u64 t; cvta.to.shared.u64 t, %1; cvt.u32.u64 %0, t; }" : "=r"(a) : "l"(p));
    return a;
}
// SW128 swizzle (Swizzle<3,4,3>) on byte offsets within a 128B-row tile
__device__ __forceinline__ uint32_t sw128(uint32_t off) { return off ^ ((off >> 3) & 0x70); }

__device__ __forceinline__ void ldsm_x4(uint32_t* r, uint32_t addr) {
    asm volatile("ldmatrix.sync.aligned.m8n8.x4.shared.b16 {%0,%1,%2,%3}, [%4];"
                 : "=r"(r[0]), "=r"(r[1]), "=r"(r[2]), "=r"(r[3]) : "r"(addr));
}
__device__ __forceinline__ void mma16816(float* c, const uint32_t* a, const uint32_t* b) {
    asm volatile(
        "mma.sync.aligned.m16n8k16.row.col.f32.bf16.bf16.f32 "
        "{%0,%1,%2,%3}, {%4,%5,%6,%7}, {%8,%9}, {%0,%1,%2,%3};"
        : "+f"(c[0]), "+f"(c[1]), "+f"(c[2]), "+f"(c[3])
        : "r"(a[0]), "r"(a[1]), "r"(a[2]), "r"(a[3]), "r"(b[0]), "r"(b[1]));
}
#define CP16(dst, src) \
    asm volatile("cp.async.cg.shared.global [%0], [%1], 16;" :: "r"(dst), "l"(src))
#define CP_COMMIT() asm volatile("cp.async.commit_group;")
#define CP_WAIT0()  asm volatile("cp.async.wait_group 0;")

// ---------------------------------------------------------------------------
// Kernel 1: row L2-normalize, bf16 emit, em_i = exp(-||fn||^2/T), zero accums.
// ---------------------------------------------------------------------------
__global__ void normalize_kernel(const float* __restrict__ feat) {
    const int r   = blockIdx.x;
    const int tid = threadIdx.x;
    __shared__ float sbuf[4];

    const float4 f4 = reinterpret_cast<const float4*>(feat + (size_t)r * D_DIM)[tid];
    float ss = f4.x * f4.x + f4.y * f4.y + f4.z * f4.z + f4.w * f4.w;
    #pragma unroll
    for (int o = 16; o; o >>= 1) ss += __shfl_xor_sync(0xffffffffu, ss, o);
    if ((tid & 31) == 0) sbuf[tid >> 5] = ss;
    __syncthreads();
    const float tot  = sbuf[0] + sbuf[1] + sbuf[2] + sbuf[3];
    const float norm = fmaxf(sqrtf(tot), 1e-8f);

    float4 fn;
    fn.x = f4.x / norm; fn.y = f4.y / norm; fn.z = f4.z / norm; fn.w = f4.w / norm;

    float ss2 = fn.x * fn.x + fn.y * fn.y + fn.z * fn.z + fn.w * fn.w;
    #pragma unroll
    for (int o = 16; o; o >>= 1) ss2 += __shfl_xor_sync(0xffffffffu, ss2, o);
    __syncthreads();
    if ((tid & 31) == 0) sbuf[tid >> 5] = ss2;
    __syncthreads();
    const float m = (sbuf[0] + sbuf[1] + sbuf[2] + sbuf[3]) * INV_T;

    __nv_bfloat162* dst =
        reinterpret_cast<__nv_bfloat162*>(g_fnb + (size_t)r * D_DIM) + tid * 2;
    dst[0] = __floats2bfloat162_rn(fn.x, fn.y);
    dst[1] = __floats2bfloat162_rn(fn.z, fn.w);

    if (tid == 0) { g_em[r] = __expf(-m); g_P[r] = 0.f; g_S[r] = 0.f; g_C[r] = 0.f; }
}

// ---------------------------------------------------------------------------
// Kernel 2: symmetric (upper-triangular) bf16 mma.sync GEMM + dual epilogue.
// 2080 CTAs, one per tile (I<=J). Off-diag tiles feed BOTH row-block I
// (row-side, masks[i,j]) and row-block J (col-side, masks[j,i]).
//
// SMEM: A 2x16384 @0 | B 2x16384 @32768 | pkR @65536 | pkC @82432 |
//       red arrays (rowPSC, colPSC, em_row, em_col) @99328 (4096B)
// ---------------------------------------------------------------------------
#define SM_A   0
#define SM_B   32768
#define SM_PKR 65536
#define SM_PKC 82432
#define SM_RED 99328
#define SMEM_BYTES (99328 + 4096)
#define K_CHUNK 64
#define N_CHUNKS (D_DIM / K_CHUNK)
#define NT 64   // tiles per dim

__global__ __launch_bounds__(256, 2)
void simloss_mma_kernel(const int* __restrict__ pos, const int* __restrict__ neg) {
    extern __shared__ char smem[];
    const uint32_t sb  = smem_u32(smem);
    const int tid    = threadIdx.x;
    const int wid    = tid >> 5;
    const int lane   = tid & 31;
    const int warp_m = wid >> 1;   // 0..3
    const int warp_n = wid & 1;    // 0..1

    // Decode upper-triangular tile (I <= J) from linear block index.
    const int bidx = blockIdx.x;
    int I = (int)(64.5f - sqrtf(64.5f * 64.5f - 2.0f * (float)bidx));
    while ((I + 1) * (129 - (I + 1)) / 2 <= bidx) ++I;
    while (I * (129 - I) / 2 > bidx) --I;
    const int J = I + (bidx - I * (129 - I) / 2);
    const bool diag = (I == J);
    const int i0 = I * 128;
    const int j0 = J * 128;

    // Reduction arrays / em caches
    float* s_rowP = reinterpret_cast<float*>(smem + SM_RED);
    float* s_rowS = s_rowP + 128;
    float* s_rowC = s_rowP + 256;
    float* s_colP = s_rowP + 384;
    float* s_colS = s_rowP + 512;
    float* s_colC = s_rowP + 640;
    float* s_emr  = s_rowP + 768;
    float* s_emc  = s_rowP + 896;

    if (tid < 128) s_emr[tid] = g_em[i0 + tid];
    else           s_emc[tid - 128] = g_em[j0 + tid - 128];
    s_rowP[tid] = 0.f; s_rowP[tid + 256] = 0.f; s_rowP[tid + 512] = 0.f;

    float acc[2][8][4];
    #pragma unroll
    for (int m = 0; m < 2; m++)
        #pragma unroll
        for (int n = 0; n < 8; n++)
            #pragma unroll
            for (int k = 0; k < 4; k++) acc[m][n][k] = 0.f;

    // cp.async staging of one K chunk
    const int st_r = tid >> 3;          // 0..31 (x4 iters -> rows)
    const int st_q = tid & 7;           // 16B col within 128B row
    auto stage = [&](int c) {
        const int b  = c & 1;
        const int kc = c * K_CHUNK;
        const __nv_bfloat16* gA = g_fnb + (size_t)i0 * D_DIM + kc;
        const __nv_bfloat16* gB = g_fnb + (size_t)j0 * D_DIM + kc;
        const uint32_t ab = sb + SM_A + b * 16384;
        const uint32_t bb = sb + SM_B + b * 16384;
        #pragma unroll
        for (int it = 0; it < 4; ++it) {
            const int r = st_r + it * 32;
            const uint32_t so = sw128(r * 128 + st_q * 16);
            CP16(ab + so, gA + (size_t)r * D_DIM + st_q * 8);
            if (!diag) CP16(bb + so, gB + (size_t)r * D_DIM + st_q * 8);
        }
        CP_COMMIT();
    };

    unsigned char* pkR = reinterpret_cast<unsigned char*>(smem) + SM_PKR;
    unsigned char* pkC = reinterpret_cast<unsigned char*>(smem) + SM_PKC;

    stage(0);

    // ldmatrix lane-address components
    const int a_row8 = (lane & 7) + ((lane >> 3) & 1) * 8;
    const int a_kb16 = (lane >> 4) * 16;
    const int b_row8 = ((lane >> 4) & 1) * 8 + (lane & 7);
    const int b_kb16 = ((lane >> 3) & 1) * 16;

    for (int c = 0; c < N_CHUNKS; ++c) {
        CP_WAIT0();
        __syncthreads();
        if (c + 1 < N_CHUNKS) stage(c + 1);

        // --- mask LDGs for this chunk's share (2 pkR units + 2 pkC units) ---
        int4 mp[4], mq[4];
        int mr[4], mg[4];
        #pragma unroll
        for (int u = 0; u < 4; ++u) {
            const int t = tid + (c * 2 + (u & 1)) * 256;   // 128 rows x 32 int4-groups
            mr[u] = t >> 5;  mg[u] = t & 31;
            if (u < 2) {
                const size_t base = (size_t)(i0 + mr[u]) * N_ROWS + (j0 + mg[u] * 4);
                mp[u] = *reinterpret_cast<const int4*>(pos + base);
                mq[u] = *reinterpret_cast<const int4*>(neg + base);
            } else if (!diag) {
                const size_t base = (size_t)(j0 + mr[u]) * N_ROWS + (i0 + mg[u] * 4);
                mp[u] = *reinterpret_cast<const int4*>(pos + base);
                mq[u] = *reinterpret_cast<const int4*>(neg + base);
            }
        }

        // --- mma over this chunk ---
        const int b = c & 1;
        const uint32_t ab = sb + SM_A + b * 16384;
        const uint32_t bb = diag ? ab : (sb + SM_B + b * 16384);
        #pragma unroll
        for (int kk = 0; kk < K_CHUNK; kk += 16) {
            uint32_t afr[2][4];
            #pragma unroll
            for (int tm = 0; tm < 2; ++tm) {
                const int row = warp_m * 32 + tm * 16 + a_row8;
                ldsm_x4(afr[tm], ab + sw128(row * 128 + kk * 2 + a_kb16));
            }
            uint32_t bfr[4][4];
            #pragma unroll
            for (int tb = 0; tb < 4; ++tb) {
                const int nr = warp_n * 64 + tb * 16 + b_row8;
                ldsm_x4(bfr[tb], bb + sw128(nr * 128 + kk * 2 + b_kb16));
            }
            #pragma unroll
            for (int tm = 0; tm < 2; ++tm)
                #pragma unroll
                for (int tn = 0; tn < 8; ++tn)
                    mma16816(acc[tm][tn], afr[tm], &bfr[tn >> 1][(tn & 1) * 2]);
        }

        // --- pack masks to smem ---
        #pragma unroll
        for (int u = 0; u < 4; ++u) {
            if (u >= 2 && diag) break;
            const int gi = (u < 2) ? (i0 + mr[u]) : (j0 + mr[u]);
            const int gj = (u < 2) ? (j0 + mg[u] * 4) : (i0 + mg[u] * 4);
            unsigned char* pk = (u < 2) ? pkR : pkC;
            uchar4 o;
            o.x = (gi != gj    ) ? (unsigned char)(((mp[u].x != 0) ? 1 : 0) | ((mq[u].x != 0) ? 2 : 0)) : 0;
            o.y = (gi != gj + 1) ? (unsigned char)(((mp[u].y != 0) ? 1 : 0) | ((mq[u].y != 0) ? 2 : 0)) : 0;
            o.z = (gi != gj + 2) ? (unsigned char)(((mp[u].z != 0) ? 1 : 0) | ((mq[u].z != 0) ? 2 : 0)) : 0;
            o.w = (gi != gj + 3) ? (unsigned char)(((mp[u].w != 0) ? 1 : 0) | ((mq[u].w != 0) ? 2 : 0)) : 0;
            *reinterpret_cast<uchar4*>(pk + mr[u] * 132 + mg[u] * 4) = o;
        }
    }
    __syncthreads();   // pk tiles + reduction arrays ready

    // ---- Dual epilogue (register-resident accs) ----
    // Element map: tile (tm,tn): rows r0 = warp_m*32+tm*16+(lane>>2), r1=r0+8;
    // cols cb = warp_n*64+tn*8+(lane&3)*2 (+1).
    const int r0b = warp_m * 32 + (lane >> 2);
    const float em0a = s_emr[r0b];
    const float em1a = s_emr[r0b + 8];
    const float em0b = s_emr[r0b + 16];
    const float em1b = s_emr[r0b + 24];

    float rP[2][2] = {{0,0},{0,0}}, rS[2][2] = {{0,0},{0,0}}, rC[2][2] = {{0,0},{0,0}};

    #pragma unroll
    for (int tn = 0; tn < 8; ++tn) {
        const int cb = warp_n * 64 + tn * 8 + (lane & 3) * 2;
        const float emc0 = s_emc[cb], emc1 = s_emc[cb + 1];
        float cP0 = 0.f, cS0 = 0.f, cC0 = 0.f, cP1 = 0.f, cS1 = 0.f, cC1 = 0.f;
        #pragma unroll
        for (int tm = 0; tm < 2; ++tm) {
            const int r0 = r0b + tm * 16;
            const int r1 = r0 + 8;
            const float em0 = tm ? em0b : em0a;
            const float em1 = tm ? em1b : em1a;
            const float E00 = __expf(acc[tm][tn][0] * INV_T);
            const float E01 = __expf(acc[tm][tn][1] * INV_T);
            const float E10 = __expf(acc[tm][tn][2] * INV_T);
            const float E11 = __expf(acc[tm][tn][3] * INV_T);

            // Row side: masks[i0+r, j0+c], weight em_row
            {
                const unsigned char b00 = pkR[r0 * 132 + cb];
                const unsigned char b01 = pkR[r0 * 132 + cb + 1];
                const unsigned char b10 = pkR[r1 * 132 + cb];
                const unsigned char b11 = pkR[r1 * 132 + cb + 1];
                const float e00 = E00 * em0, e01 = E01 * em0;
                const float e10 = E10 * em1, e11 = E11 * em1;
                if (b00 & 1) { rP[tm][0] += e00; rC[tm][0] += 1.f; }
                if (b00 & 2) { rS[tm][0] += e00; }
                if (b01 & 1) { rP[tm][0] += e01; rC[tm][0] += 1.f; }
                if (b01 & 2) { rS[tm][0] += e01; }
                if (b10 & 1) { rP[tm][1] += e10; rC[tm][1] += 1.f; }
                if (b10 & 2) { rS[tm][1] += e10; }
                if (b11 & 1) { rP[tm][1] += e11; rC[tm][1] += 1.f; }
                if (b11 & 2) { rS[tm][1] += e11; }
            }
            // Col side: masks[j0+c, i0+r], weight em_col
            if (!diag) {
                const unsigned char c00 = pkC[cb * 132 + r0];
                const unsigned char c10 = pkC[cb * 132 + r1];
                const unsigned char c01 = pkC[(cb + 1) * 132 + r0];
                const unsigned char c11 = pkC[(cb + 1) * 132 + r1];
                const float f00 = E00 * emc0, f10 = E10 * emc0;
                const float f01 = E01 * emc1, f11 = E11 * emc1;
                if (c00 & 1) { cP0 += f00; cC0 += 1.f; }
                if (c00 & 2) { cS0 += f00; }
                if (c10 & 1) { cP0 += f10; cC0 += 1.f; }
                if (c10 & 2) { cS0 += f10; }
                if (c01 & 1) { cP1 += f01; cC1 += 1.f; }
                if (c01 & 2) { cS1 += f01; }
                if (c11 & 1) { cP1 += f11; cC1 += 1.f; }
                if (c11 & 2) { cS1 += f11; }
            }
        }
        if (!diag) {
            #pragma unroll
            for (int o = 4; o < 32; o <<= 1) {
                cP0 += __shfl_xor_sync(0xffffffffu, cP0, o);
                cS0 += __shfl_xor_sync(0xffffffffu, cS0, o);
                cC0 += __shfl_xor_sync(0xffffffffu, cC0, o);
                cP1 += __shfl_xor_sync(0xffffffffu, cP1, o);
                cS1 += __shfl_xor_sync(0xffffffffu, cS1, o);
                cC1 += __shfl_xor_sync(0xffffffffu, cC1, o);
            }
            if (lane < 4) {
                atomicAdd(&s_colP[cb], cP0); atomicAdd(&s_colP[cb + 1], cP1);
                atomicAdd(&s_colS[cb], cS0); atomicAdd(&s_colS[cb + 1], cS1);
                atomicAdd(&s_colC[cb], cC0); atomicAdd(&s_colC[cb + 1], cC1);
            }
        }
    }
    // Row-side quad reduce + smem commit
    #pragma unroll
    for (int tm = 0; tm < 2; ++tm) {
        #pragma unroll
        for (int o = 1; o < 4; o <<= 1) {
            rP[tm][0] += __shfl_xor_sync(0xffffffffu, rP[tm][0], o);
            rS[tm][0] += __shfl_xor_sync(0xffffffffu, rS[tm][0], o);
            rC[tm][0] += __shfl_xor_sync(0xffffffffu, rC[tm][0], o);
            rP[tm][1] += __shfl_xor_sync(0xffffffffu, rP[tm][1], o);
            rS[tm][1] += __shfl_xor_sync(0xffffffffu, rS[tm][1], o);
            rC[tm][1] += __shfl_xor_sync(0xffffffffu, rC[tm][1], o);
        }
        if ((lane & 3) == 0) {
            const int r0 = r0b + tm * 16;
            atomicAdd(&s_rowP[r0], rP[tm][0]); atomicAdd(&s_rowP[r0 + 8], rP[tm][1]);
            atomicAdd(&s_rowS[r0], rS[tm][0]); atomicAdd(&s_rowS[r0 + 8], rS[tm][1]);
            atomicAdd(&s_rowC[r0], rC[tm][0]); atomicAdd(&s_rowC[r0 + 8], rC[tm][1]);
        }
    }
    __syncthreads();

    // Global commit: one REDG trio per row (tid<128) and per column (tid>=128).
    if (tid < 128) {
        atomicAdd(&g_P[i0 + tid], s_rowP[tid]);
        atomicAdd(&g_S[i0 + tid], s_rowS[tid]);
        atomicAdd(&g_C[i0 + tid], s_rowC[tid]);
    } else if (!diag) {
        const int c2 = tid - 128;
        atomicAdd(&g_P[j0 + c2], s_colP[c2]);
        atomicAdd(&g_S[j0 + c2], s_colS[c2]);
        atomicAdd(&g_C[j0 + c2], s_colC[c2]);
    }
}

// ---------------------------------------------------------------------------
// Kernel 3: per-row loss + mean.
// ---------------------------------------------------------------------------
__global__ void finalize_kernel(float* __restrict__ out) {
    __shared__ float sbuf[32];
    const int tid = threadIdx.x;
    float local = 0.f;
    for (int i = tid; i < N_ROWS; i += 1024) {
        const float C = g_C[i];
        const float P = g_P[i];
        const float S = g_S[i];
        const float L = logf(S);
        const float card = (C == 0.f) ? 1.f : C;
        local += -(P - C * L) / card;
    }
    #pragma unroll
    for (int o = 16; o; o >>= 1) local += __shfl_xor_sync(0xffffffffu, local, o);
    if ((tid & 31) == 0) sbuf[tid >> 5] = local;
    __syncthreads();
    if (tid < 32) {
        float v = sbuf[tid];
        #pragma unroll
        for (int o = 16; o; o >>= 1) v += __shfl_xor_sync(0xffffffffu, v, o);
        if (tid == 0) out[0] = v * (1.0f / (float)N_ROWS);
    }
}

// ---------------------------------------------------------------------------
extern "C" void kernel_launch(void* const* d_in, const int* in_sizes, int n_in,
                              void* d_out, int out_size) {
    const float* feat = (const float*)d_in[0];
    const int*   pos  = (const int*)d_in[1];
    const int*   neg  = (const int*)d_in[2];
    float*       out  = (float*)d_out;

    cudaFuncSetAttribute(simloss_mma_kernel,
                         cudaFuncAttributeMaxDynamicSharedMemorySize, SMEM_BYTES);

    normalize_kernel<<<N_ROWS, 128>>>(feat);

    simloss_mma_kernel<<<NT * (NT + 1) / 2, 256, SMEM_BYTES>>>(pos, neg);

    finalize_kernel<<<1, 1024>>>(out);
}